// round 15
// baseline (speedup 1.0000x reference)
#include <cuda_runtime.h>
#include <cstdint>

// ─── Problem constants ─────────────────────────────────────────────────────
#define BATCH   8
#define LEN     4096
#define NK      128
#define NSTATE  256
#define M_TOTAL (BATCH*LEN)
#define NCH     128          // scan chunks per sequence
#define LC      32           // chunk length
#define LOG2LC  5
#define OUT_Y   ((size_t)BATCH*LEN*NSTATE)

// ─── Scratch (device globals; no allocation allowed) ───────────────────────
__device__ float  g_uB[(size_t)M_TOTAL * NSTATE];
__device__ float  g_x [(size_t)M_TOTAL * NSTATE];
__device__ float2 g_h   [BATCH * NCH * NK];
__device__ float2 g_init[BATCH * NCH * NK];
__device__ float  g_Bt[NSTATE * NSTATE];     // B^T  (K-major [N,K])
__device__ float  g_Ct[NSTATE * NSTATE];     // C^T

// ─── TF32 mma.sync GEMM, cp.async 3-stage pipeline ─────────────────────────
// C[M,256] = A[M,256] @ Bt^T  (A row-major [M,K], Bt row-major [N,K])
// CTA tile 128x256x32, 256 threads = 8 warps (2 M-warps x 4 N-warps),
// warp tile 64x64 = 4x8 m16n8k8 fragments.
#define BM 128
#define BN 256
#define BK 32
#define KTILES (NSTATE / BK)          // 8
#define STAGES 3
#define APAD 36                       // padded row stride in floats
#define A_STAGE (BM * APAD)           // 4608 floats
#define B_STAGE (BN * APAD)           // 9216 floats
#define STAGE_FLOATS (A_STAGE + B_STAGE)
#define SMEM_FLOATS (STAGES * STAGE_FLOATS)
#define SMEM_BYTES (SMEM_FLOATS * 4)  // 165888 B

__device__ __forceinline__ uint32_t smem_to_u32(const void* p) {
    uint32_t a;
    asm("{ .reg .u64 t; cvta.to.shared.u64 t, %1; cvt.u32.u64 %0, t; }"
        : "=r"(a) : "l"(p));
    return a;
}
__device__ __forceinline__ void cp_async16(uint32_t dst, const float* src) {
    asm volatile("cp.async.cg.shared.global [%0], [%1], 16;"
                 :: "r"(dst), "l"(src) : "memory");
}
#define CP_COMMIT() asm volatile("cp.async.commit_group;" ::: "memory")
#define CP_WAIT2()  asm volatile("cp.async.wait_group 2;"  ::: "memory")

__device__ __forceinline__ uint32_t f2tf32(float x) {
    uint32_t r;
    asm("cvt.rna.tf32.f32 %0, %1;" : "=r"(r) : "f"(x));
    return r;
}
__device__ __forceinline__ void mma_tf32(float* c, const uint32_t* a, const uint32_t* b)
{
    asm volatile(
        "mma.sync.aligned.m16n8k8.row.col.f32.tf32.tf32.f32 "
        "{%0,%1,%2,%3}, {%4,%5,%6,%7}, {%8,%9}, {%0,%1,%2,%3};"
        : "+f"(c[0]), "+f"(c[1]), "+f"(c[2]), "+f"(c[3])
        : "r"(a[0]), "r"(a[1]), "r"(a[2]), "r"(a[3]), "r"(b[0]), "r"(b[1]));
}

__global__ __launch_bounds__(256, 1) void gemm_tf32(
    const float* __restrict__ Am, const float* __restrict__ Bt,
    float* __restrict__ Cm)
{
    extern __shared__ float smem_f[];
    const uint32_t sb = smem_to_u32(smem_f);

    const int tid = threadIdx.x;
    const int wid = tid >> 5;
    const int lid = tid & 31;
    const int gid = lid >> 2;          // 0..7
    const int tig = lid & 3;           // 0..3
    const int warpM = wid & 1;         // 0..1  (64-row slabs)
    const int warpN = wid >> 1;        // 0..3  (64-col slabs)
    const int blockRow = blockIdx.y * BM;

    const float* Arow = Am + (size_t)blockRow * NSTATE;
    const float* Brow = Bt;            // full N per CTA

    // Per-thread async-copy mapping (16B chunks): chunk f -> row f>>3, quad f&7
    auto load_tile = [&](int kt, int st) {
        const uint32_t abase = sb + (uint32_t)(st * STAGE_FLOATS) * 4u;
        const uint32_t bbase = abase + (uint32_t)A_STAGE * 4u;
#pragma unroll
        for (int i = 0; i < 4; i++) {            // A: 1024 chunks / 256 thr
            int f = tid + i * 256;
            int r = f >> 3, q = f & 7;
            cp_async16(abase + (uint32_t)(r * APAD + q * 4) * 4u,
                       Arow + (size_t)r * NSTATE + kt * BK + q * 4);
        }
#pragma unroll
        for (int i = 0; i < 8; i++) {            // B: 2048 chunks / 256 thr
            int f = tid + i * 256;
            int r = f >> 3, q = f & 7;
            cp_async16(bbase + (uint32_t)(r * APAD + q * 4) * 4u,
                       Brow + (size_t)r * NSTATE + kt * BK + q * 4);
        }
    };

    float c[4][8][4];
#pragma unroll
    for (int mf = 0; mf < 4; mf++)
#pragma unroll
        for (int nf = 0; nf < 8; nf++)
#pragma unroll
            for (int j = 0; j < 4; j++) c[mf][nf][j] = 0.f;

    // Prologue: tiles 0 and 1 in flight
    load_tile(0, 0); CP_COMMIT();
    load_tile(1, 1); CP_COMMIT();

    for (int kt = 0; kt < KTILES; kt++) {
        __syncthreads();                         // stage (kt+2)%3 free to rewrite
        if (kt + 2 < KTILES) load_tile(kt + 2, (kt + 2) % STAGES);
        CP_COMMIT();
        CP_WAIT2();                              // tile kt resident
        __syncthreads();

        const float* As = smem_f + (size_t)(kt % STAGES) * STAGE_FLOATS;
        const float* Bs = As + A_STAGE;
#pragma unroll
        for (int ks = 0; ks < 4; ks++) {
            const int k0 = ks * 8;
            uint32_t af[4][4];
#pragma unroll
            for (int mf = 0; mf < 4; mf++) {
                int r0 = warpM * 64 + mf * 16 + gid;
                af[mf][0] = f2tf32(As[(size_t)(r0    ) * APAD + k0 + tig    ]);
                af[mf][1] = f2tf32(As[(size_t)(r0 + 8) * APAD + k0 + tig    ]);
                af[mf][2] = f2tf32(As[(size_t)(r0    ) * APAD + k0 + tig + 4]);
                af[mf][3] = f2tf32(As[(size_t)(r0 + 8) * APAD + k0 + tig + 4]);
            }
            uint32_t bf[8][2];
#pragma unroll
            for (int nf = 0; nf < 8; nf++) {
                int n0 = warpN * 64 + nf * 8 + gid;
                bf[nf][0] = f2tf32(Bs[(size_t)n0 * APAD + k0 + tig    ]);
                bf[nf][1] = f2tf32(Bs[(size_t)n0 * APAD + k0 + tig + 4]);
            }
#pragma unroll
            for (int mf = 0; mf < 4; mf++)
#pragma unroll
                for (int nf = 0; nf < 8; nf++)
                    mma_tf32(c[mf][nf], af[mf], bf[nf]);
        }
    }

    // Epilogue: c0,c1 at (row, 2*tig), c2,c3 at (row+8, 2*tig)
#pragma unroll
    for (int mf = 0; mf < 4; mf++) {
        int row = blockRow + warpM * 64 + mf * 16 + gid;
#pragma unroll
        for (int nf = 0; nf < 8; nf++) {
            int col = warpN * 64 + nf * 8 + tig * 2;
            *(float2*)(Cm + (size_t)row * NSTATE + col) =
                make_float2(c[mf][nf][0], c[mf][nf][1]);
            *(float2*)(Cm + (size_t)(row + 8) * NSTATE + col) =
                make_float2(c[mf][nf][2], c[mf][nf][3]);
        }
    }
}

// ─── 256x256 transpose (tiny, once per launch) ─────────────────────────────
__global__ __launch_bounds__(256) void transpose256(
    const float* __restrict__ in, float* __restrict__ out)
{
    int n = blockIdx.x;          // output row
    int k = threadIdx.x;         // output col
    out[n * 256 + k] = in[k * 256 + n];
}

// ─── Scan phase 1: per-chunk local scan (zero init) ────────────────────────
__global__ __launch_bounds__(NK) void scan_partial(const float* __restrict__ A)
{
    const int k  = threadIdx.x;
    const int ch = blockIdx.x;
    const int b  = blockIdx.y;
    const float c = A[4 * k + 0];
    const float s = A[4 * k + 1];

    const float2* base = reinterpret_cast<const float2*>(g_uB)
                       + (size_t)(b * LEN + ch * LC) * NK + k;
    float zx = 0.f, zy = 0.f;
#pragma unroll 8
    for (int l = 0; l < LC; l++) {
        float2 w = base[(size_t)l * NK];
        float nx = fmaf(zx, c, fmaf(-zy, s, w.x));
        float ny = fmaf(zx, s, fmaf( zy, c, w.y));
        zx = nx; zy = ny;
    }
    g_h[((size_t)b * NCH + ch) * NK + k] = make_float2(zx, zy);
}

// ─── Scan phase 2: cross-chunk prefix (R^LC via double-prec doubling) ──────
__global__ __launch_bounds__(NK) void scan_prefix(
    const float* __restrict__ A, const float* __restrict__ x0)
{
    const int k = threadIdx.x;
    const int b = blockIdx.x;

    double cd = (double)A[4 * k + 0];
    double sd = (double)A[4 * k + 1];
#pragma unroll
    for (int i = 0; i < LOG2LC; i++) {
        double nc = cd * cd - sd * sd;
        double ns = 2.0 * cd * sd;
        cd = nc; sd = ns;
    }
    const float Cc = (float)cd, Ss = (float)sd;

    float zx = x0[((size_t)b * NK + k) * 2 + 0];
    float zy = x0[((size_t)b * NK + k) * 2 + 1];
    for (int ch = 0; ch < NCH; ch++) {
        size_t idx = ((size_t)b * NCH + ch) * NK + k;
        g_init[idx] = make_float2(zx, zy);
        float2 h = g_h[idx];
        float nx = fmaf(zx, Cc, fmaf(-zy, Ss, h.x));
        float ny = fmaf(zx, Ss, fmaf( zy, Cc, h.y));
        zx = nx; zy = ny;
    }
}

// ─── Scan phase 3: replay, write x and new_state ───────────────────────────
__global__ __launch_bounds__(NK) void scan_replay(
    const float* __restrict__ A, float* __restrict__ out)
{
    const int k  = threadIdx.x;
    const int ch = blockIdx.x;
    const int b  = blockIdx.y;
    const float c = A[4 * k + 0];
    const float s = A[4 * k + 1];

    const size_t idx = ((size_t)b * NCH + ch) * NK + k;
    float2 z0 = g_init[idx];
    float zx = z0.x, zy = z0.y;

    const float2* src = reinterpret_cast<const float2*>(g_uB)
                      + (size_t)(b * LEN + ch * LC) * NK + k;
    float2* dst = reinterpret_cast<float2*>(g_x)
                + (size_t)(b * LEN + ch * LC) * NK + k;

#pragma unroll 8
    for (int l = 0; l < LC; l++) {
        float2 w = src[(size_t)l * NK];
        float nx = fmaf(zx, c, fmaf(-zy, s, w.x));
        float ny = fmaf(zx, s, fmaf( zy, c, w.y));
        zx = nx; zy = ny;
        dst[(size_t)l * NK] = make_float2(zx, zy);
    }
    if (ch == NCH - 1) {
        out[OUT_Y + ((size_t)b * NK + k) * 2 + 0] = zx;
        out[OUT_Y + ((size_t)b * NK + k) * 2 + 1] = zy;
    }
}

// ─── Launch ────────────────────────────────────────────────────────────────
extern "C" void kernel_launch(void* const* d_in, const int* in_sizes, int n_in,
                              void* d_out, int out_size)
{
    const float* u  = (const float*)d_in[0];
    const float* x0 = (const float*)d_in[1];
    const float* A  = (const float*)d_in[2];
    const float* B  = (const float*)d_in[3];
    const float* C  = (const float*)d_in[4];
    float* out = (float*)d_out;
    (void)in_sizes; (void)n_in; (void)out_size;

    float *uBp, *xp, *Btp, *Ctp;
    cudaGetSymbolAddress((void**)&uBp, g_uB);
    cudaGetSymbolAddress((void**)&xp,  g_x);
    cudaGetSymbolAddress((void**)&Btp, g_Bt);
    cudaGetSymbolAddress((void**)&Ctp, g_Ct);

    cudaFuncSetAttribute(gemm_tf32, cudaFuncAttributeMaxDynamicSharedMemorySize, SMEM_BYTES);

    transpose256<<<NSTATE, NSTATE>>>(B, Btp);
    transpose256<<<NSTATE, NSTATE>>>(C, Ctp);

    dim3 gemm_grid(1, M_TOTAL / BM);               // (1, 256)
    gemm_tf32<<<gemm_grid, 256, SMEM_BYTES>>>(u, Btp, uBp);

    scan_partial<<<dim3(NCH, BATCH), NK>>>(A);
    scan_prefix<<<BATCH, NK>>>(A, x0);
    scan_replay<<<dim3(NCH, BATCH), NK>>>(A, out);

    gemm_tf32<<<gemm_grid, 256, SMEM_BYTES>>>(xp, Ctp, out);
}

// round 16
// speedup vs baseline: 1.1938x; 1.1938x over previous
#include <cuda_runtime.h>
#include <cuda_fp16.h>
#include <cstdint>

// ─── Problem constants ─────────────────────────────────────────────────────
#define BATCH   8
#define LEN     4096
#define NK      128
#define NSTATE  256
#define M_TOTAL (BATCH*LEN)
#define NCH     128          // scan chunks per sequence
#define LC      32           // chunk length
#define LOG2LC  5
#define OUT_Y   ((size_t)BATCH*LEN*NSTATE)

// ─── Scratch (device globals; no allocation allowed) ───────────────────────
__device__ float  g_uB[(size_t)M_TOTAL * NSTATE];      // u@B (fp32, scan input)
__device__ __half g_uh[(size_t)M_TOTAL * NSTATE];      // u as fp16 (GEMM1 A)
__device__ __half g_xh[(size_t)M_TOTAL * NSTATE];      // x as fp16 (GEMM2 A)
__device__ float2 g_h   [BATCH * NCH * NK];
__device__ float2 g_init[BATCH * NCH * NK];
__device__ __half g_Bth[NSTATE * NSTATE];              // B^T fp16 (K-major [N,K])
__device__ __half g_Cth[NSTATE * NSTATE];              // C^T fp16

// ─── FP16 mma.sync GEMM, cp.async 3-stage pipeline ─────────────────────────
// C[M,256] = A[M,256] @ Bt^T  (A half row-major [M,K], Bt half row-major [N,K])
// CTA tile 128x256x32, 256 threads = 8 warps (2 M-warps x 4 N-warps),
// warp tile 64x64 = 4x8 m16n8k16 fragments.
#define BM 128
#define BN 256
#define BK 32
#define KTILES (NSTATE / BK)          // 8
#define STAGES 3
#define HPAD 40                       // padded row stride in halves (80 B)
#define A_STAGE_H (BM * HPAD)         // 5120 halves
#define B_STAGE_H (BN * HPAD)         // 10240 halves
#define STAGE_H   (A_STAGE_H + B_STAGE_H)
#define SMEM_BYTES (STAGES * STAGE_H * 2)   // 92160 B

__device__ __forceinline__ uint32_t smem_to_u32(const void* p) {
    uint32_t a;
    asm("{ .reg .u64 t; cvta.to.shared.u64 t, %1; cvt.u32.u64 %0, t; }"
        : "=r"(a) : "l"(p));
    return a;
}
__device__ __forceinline__ void cp_async16(uint32_t dst, const __half* src) {
    asm volatile("cp.async.cg.shared.global [%0], [%1], 16;"
                 :: "r"(dst), "l"(src) : "memory");
}
#define CP_COMMIT() asm volatile("cp.async.commit_group;" ::: "memory")
#define CP_WAIT2()  asm volatile("cp.async.wait_group 2;"  ::: "memory")

__device__ __forceinline__ void mma_f16(float* c, const uint32_t* a, const uint32_t* b)
{
    asm volatile(
        "mma.sync.aligned.m16n8k16.row.col.f32.f16.f16.f32 "
        "{%0,%1,%2,%3}, {%4,%5,%6,%7}, {%8,%9}, {%0,%1,%2,%3};"
        : "+f"(c[0]), "+f"(c[1]), "+f"(c[2]), "+f"(c[3])
        : "r"(a[0]), "r"(a[1]), "r"(a[2]), "r"(a[3]), "r"(b[0]), "r"(b[1]));
}

__global__ __launch_bounds__(256, 1) void gemm_f16(
    const __half* __restrict__ Ah, const __half* __restrict__ Bh,
    float* __restrict__ Cm)
{
    extern __shared__ __half smem_h[];
    const uint32_t sb = smem_to_u32(smem_h);

    const int tid = threadIdx.x;
    const int wid = tid >> 5;
    const int lid = tid & 31;
    const int gid = lid >> 2;          // 0..7
    const int tig = lid & 3;           // 0..3
    const int warpM = wid & 1;         // 0..1  (64-row slabs)
    const int warpN = wid >> 1;        // 0..3  (64-col slabs)
    const int blockRow = blockIdx.y * BM;

    const __half* Arow = Ah + (size_t)blockRow * NSTATE;
    const __half* Brow = Bh;           // full N per CTA

    // Per-thread async-copy mapping (16B = 8 halves): chunk f -> row f>>2, quad f&3
    auto load_tile = [&](int kt, int st) {
        const uint32_t abase = sb + (uint32_t)(st * STAGE_H) * 2u;
        const uint32_t bbase = abase + (uint32_t)A_STAGE_H * 2u;
#pragma unroll
        for (int i = 0; i < 2; i++) {            // A: 512 chunks / 256 thr
            int f = tid + i * 256;
            int r = f >> 2, q = f & 3;
            cp_async16(abase + (uint32_t)(r * HPAD + q * 8) * 2u,
                       Arow + (size_t)r * NSTATE + kt * BK + q * 8);
        }
#pragma unroll
        for (int i = 0; i < 4; i++) {            // B: 1024 chunks / 256 thr
            int f = tid + i * 256;
            int r = f >> 2, q = f & 3;
            cp_async16(bbase + (uint32_t)(r * HPAD + q * 8) * 2u,
                       Brow + (size_t)r * NSTATE + kt * BK + q * 8);
        }
    };

    float c[4][8][4];
#pragma unroll
    for (int mf = 0; mf < 4; mf++)
#pragma unroll
        for (int nf = 0; nf < 8; nf++)
#pragma unroll
            for (int j = 0; j < 4; j++) c[mf][nf][j] = 0.f;

    load_tile(0, 0); CP_COMMIT();
    load_tile(1, 1); CP_COMMIT();

    for (int kt = 0; kt < KTILES; kt++) {
        __syncthreads();                         // stage (kt+2)%3 free to rewrite
        if (kt + 2 < KTILES) load_tile(kt + 2, (kt + 2) % STAGES);
        CP_COMMIT();
        CP_WAIT2();                              // tile kt resident
        __syncthreads();

        const __half* As = smem_h + (size_t)(kt % STAGES) * STAGE_H;
        const __half* Bs = As + A_STAGE_H;
#pragma unroll
        for (int ks = 0; ks < 2; ks++) {         // two k16 slabs per BK=32
            const int k0 = ks * 16;
            uint32_t af[4][4];
#pragma unroll
            for (int mf = 0; mf < 4; mf++) {
                int r0 = warpM * 64 + mf * 16 + gid;
                af[mf][0] = *(const uint32_t*)(As + (size_t)(r0    ) * HPAD + k0 + 2 * tig    );
                af[mf][1] = *(const uint32_t*)(As + (size_t)(r0 + 8) * HPAD + k0 + 2 * tig    );
                af[mf][2] = *(const uint32_t*)(As + (size_t)(r0    ) * HPAD + k0 + 2 * tig + 8);
                af[mf][3] = *(const uint32_t*)(As + (size_t)(r0 + 8) * HPAD + k0 + 2 * tig + 8);
            }
            uint32_t bf[8][2];
#pragma unroll
            for (int nf = 0; nf < 8; nf++) {
                int n0 = warpN * 64 + nf * 8 + gid;
                bf[nf][0] = *(const uint32_t*)(Bs + (size_t)n0 * HPAD + k0 + 2 * tig    );
                bf[nf][1] = *(const uint32_t*)(Bs + (size_t)n0 * HPAD + k0 + 2 * tig + 8);
            }
#pragma unroll
            for (int mf = 0; mf < 4; mf++)
#pragma unroll
                for (int nf = 0; nf < 8; nf++)
                    mma_f16(c[mf][nf], af[mf], bf[nf]);
        }
    }

    // Epilogue: c0,c1 at (row, 2*tig), c2,c3 at (row+8, 2*tig)
#pragma unroll
    for (int mf = 0; mf < 4; mf++) {
        int row = blockRow + warpM * 64 + mf * 16 + gid;
#pragma unroll
        for (int nf = 0; nf < 8; nf++) {
            int col = warpN * 64 + nf * 8 + tig * 2;
            *(float2*)(Cm + (size_t)row * NSTATE + col) =
                make_float2(c[mf][nf][0], c[mf][nf][1]);
            *(float2*)(Cm + (size_t)(row + 8) * NSTATE + col) =
                make_float2(c[mf][nf][2], c[mf][nf][3]);
        }
    }
}

// ─── u (fp32) -> fp16, pure bandwidth pass ─────────────────────────────────
__global__ __launch_bounds__(256) void convert_u_f16(
    const float* __restrict__ in, __half* __restrict__ out)
{
    size_t t = (size_t)blockIdx.x * 256 + threadIdx.x;   // one float4 each
    float4 v = *(const float4*)(in + t * 4);
    __half2* o = (__half2*)(out + t * 4);
    o[0] = __floats2half2_rn(v.x, v.y);
    o[1] = __floats2half2_rn(v.z, v.w);
}

// ─── 256x256 transpose + convert to half (tiny) ────────────────────────────
__global__ __launch_bounds__(256) void transpose256_f16(
    const float* __restrict__ in, __half* __restrict__ out)
{
    int n = blockIdx.x;          // output row
    int k = threadIdx.x;         // output col
    out[n * 256 + k] = __float2half_rn(in[k * 256 + n]);
}

// ─── Scan phase 1: per-chunk local scan (zero init) ────────────────────────
__global__ __launch_bounds__(NK) void scan_partial(const float* __restrict__ A)
{
    const int k  = threadIdx.x;
    const int ch = blockIdx.x;
    const int b  = blockIdx.y;
    const float c = A[4 * k + 0];
    const float s = A[4 * k + 1];

    const float2* base = reinterpret_cast<const float2*>(g_uB)
                       + (size_t)(b * LEN + ch * LC) * NK + k;
    float zx = 0.f, zy = 0.f;
#pragma unroll 8
    for (int l = 0; l < LC; l++) {
        float2 w = base[(size_t)l * NK];
        float nx = fmaf(zx, c, fmaf(-zy, s, w.x));
        float ny = fmaf(zx, s, fmaf( zy, c, w.y));
        zx = nx; zy = ny;
    }
    g_h[((size_t)b * NCH + ch) * NK + k] = make_float2(zx, zy);
}

// ─── Scan phase 2: cross-chunk prefix (R^LC via double-prec doubling) ──────
__global__ __launch_bounds__(NK) void scan_prefix(
    const float* __restrict__ A, const float* __restrict__ x0)
{
    const int k = threadIdx.x;
    const int b = blockIdx.x;

    double cd = (double)A[4 * k + 0];
    double sd = (double)A[4 * k + 1];
#pragma unroll
    for (int i = 0; i < LOG2LC; i++) {
        double nc = cd * cd - sd * sd;
        double ns = 2.0 * cd * sd;
        cd = nc; sd = ns;
    }
    const float Cc = (float)cd, Ss = (float)sd;

    float zx = x0[((size_t)b * NK + k) * 2 + 0];
    float zy = x0[((size_t)b * NK + k) * 2 + 1];
    for (int ch = 0; ch < NCH; ch++) {
        size_t idx = ((size_t)b * NCH + ch) * NK + k;
        g_init[idx] = make_float2(zx, zy);
        float2 h = g_h[idx];
        float nx = fmaf(zx, Cc, fmaf(-zy, Ss, h.x));
        float ny = fmaf(zx, Ss, fmaf( zy, Cc, h.y));
        zx = nx; zy = ny;
    }
}

// ─── Scan phase 3: replay, write x (fp16) and new_state (fp32) ─────────────
__global__ __launch_bounds__(NK) void scan_replay(
    const float* __restrict__ A, float* __restrict__ out)
{
    const int k  = threadIdx.x;
    const int ch = blockIdx.x;
    const int b  = blockIdx.y;
    const float c = A[4 * k + 0];
    const float s = A[4 * k + 1];

    const size_t idx = ((size_t)b * NCH + ch) * NK + k;
    float2 z0 = g_init[idx];
    float zx = z0.x, zy = z0.y;

    const float2* src = reinterpret_cast<const float2*>(g_uB)
                      + (size_t)(b * LEN + ch * LC) * NK + k;
    __half2* dst = reinterpret_cast<__half2*>(g_xh)
                 + (size_t)(b * LEN + ch * LC) * NK + k;

#pragma unroll 8
    for (int l = 0; l < LC; l++) {
        float2 w = src[(size_t)l * NK];
        float nx = fmaf(zx, c, fmaf(-zy, s, w.x));
        float ny = fmaf(zx, s, fmaf( zy, c, w.y));
        zx = nx; zy = ny;
        dst[(size_t)l * NK] = __floats2half2_rn(zx, zy);
    }
    if (ch == NCH - 1) {
        out[OUT_Y + ((size_t)b * NK + k) * 2 + 0] = zx;
        out[OUT_Y + ((size_t)b * NK + k) * 2 + 1] = zy;
    }
}

// ─── Launch ────────────────────────────────────────────────────────────────
extern "C" void kernel_launch(void* const* d_in, const int* in_sizes, int n_in,
                              void* d_out, int out_size)
{
    const float* u  = (const float*)d_in[0];
    const float* x0 = (const float*)d_in[1];
    const float* A  = (const float*)d_in[2];
    const float* B  = (const float*)d_in[3];
    const float* C  = (const float*)d_in[4];
    float* out = (float*)d_out;
    (void)in_sizes; (void)n_in; (void)out_size;

    float  *uBp;
    __half *uhp, *xhp, *Bthp, *Cthp;
    cudaGetSymbolAddress((void**)&uBp,  g_uB);
    cudaGetSymbolAddress((void**)&uhp,  g_uh);
    cudaGetSymbolAddress((void**)&xhp,  g_xh);
    cudaGetSymbolAddress((void**)&Bthp, g_Bth);
    cudaGetSymbolAddress((void**)&Cthp, g_Cth);

    cudaFuncSetAttribute(gemm_f16, cudaFuncAttributeMaxDynamicSharedMemorySize, SMEM_BYTES);

    transpose256_f16<<<NSTATE, NSTATE>>>(B, Bthp);
    transpose256_f16<<<NSTATE, NSTATE>>>(C, Cthp);
    convert_u_f16<<<((size_t)M_TOTAL * NSTATE / 4 + 255) / 256, 256>>>(u, uhp);

    dim3 gemm_grid(1, M_TOTAL / BM);               // (1, 256)
    gemm_f16<<<gemm_grid, 256, SMEM_BYTES>>>(uhp, Bthp, uBp);

    scan_partial<<<dim3(NCH, BATCH), NK>>>(A);
    scan_prefix<<<BATCH, NK>>>(A, x0);
    scan_replay<<<dim3(NCH, BATCH), NK>>>(A, out);

    gemm_f16<<<gemm_grid, 256, SMEM_BYTES>>>(xhp, Cthp, out);
}

// round 17
// speedup vs baseline: 1.1963x; 1.0021x over previous
#include <cuda_runtime.h>
#include <cuda_fp16.h>
#include <cstdint>

// ─── Problem constants ─────────────────────────────────────────────────────
#define BATCH   8
#define LEN     4096
#define NK      128
#define NSTATE  256
#define M_TOTAL (BATCH*LEN)
#define NCH     128          // scan chunks per sequence
#define LC      32           // chunk length
#define LOG2LC  5
#define OUT_Y   ((size_t)BATCH*LEN*NSTATE)

// ─── Scratch (device globals; no allocation allowed) ───────────────────────
__device__ float  g_uB[(size_t)M_TOTAL * NSTATE];      // u@B (fp32, scan input)
__device__ __half g_uh[(size_t)M_TOTAL * NSTATE];      // u as fp16 (GEMM1 A)
__device__ __half g_xh[(size_t)M_TOTAL * NSTATE];      // x as fp16 (GEMM2 A)
__device__ float2 g_h   [BATCH * NCH * NK];
__device__ float2 g_init[BATCH * NCH * NK];
__device__ __half g_Bth[NSTATE * NSTATE];              // B^T fp16 (K-major [N,K])
__device__ __half g_Cth[NSTATE * NSTATE];              // C^T fp16

// ─── FP16 mma.sync GEMM, cp.async 3-stage pipeline ─────────────────────────
// C[M,256] = A[M,256] @ Bt^T  (A half row-major [M,K], Bt half row-major [N,K])
// CTA tile 128x128x32, 256 threads = 8 warps (2 M-warps x 4 N-warps),
// warp tile 64x32 = 4x4 m16n8k16 fragments. 2 CTAs/SM for latency hiding.
#define BM 128
#define BN 128
#define BK 32
#define KTILES (NSTATE / BK)          // 8
#define STAGES 3
#define HPAD 40                       // padded row stride in halves (80 B)
#define A_STAGE_H (BM * HPAD)         // 5120 halves
#define B_STAGE_H (BN * HPAD)         // 5120 halves
#define STAGE_H   (A_STAGE_H + B_STAGE_H)
#define SMEM_BYTES (STAGES * STAGE_H * 2)   // 61440 B

__device__ __forceinline__ uint32_t smem_to_u32(const void* p) {
    uint32_t a;
    asm("{ .reg .u64 t; cvta.to.shared.u64 t, %1; cvt.u32.u64 %0, t; }"
        : "=r"(a) : "l"(p));
    return a;
}
__device__ __forceinline__ void cp_async16(uint32_t dst, const __half* src) {
    asm volatile("cp.async.cg.shared.global [%0], [%1], 16;"
                 :: "r"(dst), "l"(src) : "memory");
}
#define CP_COMMIT() asm volatile("cp.async.commit_group;" ::: "memory")
#define CP_WAIT2()  asm volatile("cp.async.wait_group 2;"  ::: "memory")

__device__ __forceinline__ void mma_f16(float* c, const uint32_t* a, const uint32_t* b)
{
    asm volatile(
        "mma.sync.aligned.m16n8k16.row.col.f32.f16.f16.f32 "
        "{%0,%1,%2,%3}, {%4,%5,%6,%7}, {%8,%9}, {%0,%1,%2,%3};"
        : "+f"(c[0]), "+f"(c[1]), "+f"(c[2]), "+f"(c[3])
        : "r"(a[0]), "r"(a[1]), "r"(a[2]), "r"(a[3]), "r"(b[0]), "r"(b[1]));
}

__global__ __launch_bounds__(256, 2) void gemm_f16(
    const __half* __restrict__ Ah, const __half* __restrict__ Bh,
    float* __restrict__ Cm)
{
    extern __shared__ __half smem_h[];
    const uint32_t sb = smem_to_u32(smem_h);

    const int tid = threadIdx.x;
    const int wid = tid >> 5;
    const int lid = tid & 31;
    const int gid = lid >> 2;          // 0..7
    const int tig = lid & 3;           // 0..3
    const int warpM = wid & 1;         // 0..1  (64-row slabs)
    const int warpN = wid >> 1;        // 0..3  (32-col slabs)
    const int blockRow = blockIdx.y * BM;
    const int blockCol = blockIdx.x * BN;

    const __half* Arow = Ah + (size_t)blockRow * NSTATE;
    const __half* Brow = Bh + (size_t)blockCol * NSTATE;

    // Per-thread async-copy mapping (16B = 8 halves): chunk f -> row f>>2, quad f&3
    auto load_tile = [&](int kt, int st) {
        const uint32_t abase = sb + (uint32_t)(st * STAGE_H) * 2u;
        const uint32_t bbase = abase + (uint32_t)A_STAGE_H * 2u;
#pragma unroll
        for (int i = 0; i < 2; i++) {            // A: 512 chunks / 256 thr
            int f = tid + i * 256;
            int r = f >> 2, q = f & 3;
            cp_async16(abase + (uint32_t)(r * HPAD + q * 8) * 2u,
                       Arow + (size_t)r * NSTATE + kt * BK + q * 8);
        }
#pragma unroll
        for (int i = 0; i < 2; i++) {            // B: 512 chunks / 256 thr
            int f = tid + i * 256;
            int r = f >> 2, q = f & 3;
            cp_async16(bbase + (uint32_t)(r * HPAD + q * 8) * 2u,
                       Brow + (size_t)r * NSTATE + kt * BK + q * 8);
        }
    };

    float c[4][4][4];
#pragma unroll
    for (int mf = 0; mf < 4; mf++)
#pragma unroll
        for (int nf = 0; nf < 4; nf++)
#pragma unroll
            for (int j = 0; j < 4; j++) c[mf][nf][j] = 0.f;

    load_tile(0, 0); CP_COMMIT();
    load_tile(1, 1); CP_COMMIT();

    for (int kt = 0; kt < KTILES; kt++) {
        __syncthreads();                         // stage (kt+2)%3 free to rewrite
        if (kt + 2 < KTILES) load_tile(kt + 2, (kt + 2) % STAGES);
        CP_COMMIT();
        CP_WAIT2();                              // tile kt resident
        __syncthreads();

        const __half* As = smem_h + (size_t)(kt % STAGES) * STAGE_H;
        const __half* Bs = As + A_STAGE_H;
#pragma unroll
        for (int ks = 0; ks < 2; ks++) {         // two k16 slabs per BK=32
            const int k0 = ks * 16;
            uint32_t af[4][4];
#pragma unroll
            for (int mf = 0; mf < 4; mf++) {
                int r0 = warpM * 64 + mf * 16 + gid;
                af[mf][0] = *(const uint32_t*)(As + (size_t)(r0    ) * HPAD + k0 + 2 * tig    );
                af[mf][1] = *(const uint32_t*)(As + (size_t)(r0 + 8) * HPAD + k0 + 2 * tig    );
                af[mf][2] = *(const uint32_t*)(As + (size_t)(r0    ) * HPAD + k0 + 2 * tig + 8);
                af[mf][3] = *(const uint32_t*)(As + (size_t)(r0 + 8) * HPAD + k0 + 2 * tig + 8);
            }
            uint32_t bf[4][2];
#pragma unroll
            for (int nf = 0; nf < 4; nf++) {
                int n0 = warpN * 32 + nf * 8 + gid;
                bf[nf][0] = *(const uint32_t*)(Bs + (size_t)n0 * HPAD + k0 + 2 * tig    );
                bf[nf][1] = *(const uint32_t*)(Bs + (size_t)n0 * HPAD + k0 + 2 * tig + 8);
            }
#pragma unroll
            for (int mf = 0; mf < 4; mf++)
#pragma unroll
                for (int nf = 0; nf < 4; nf++)
                    mma_f16(c[mf][nf], af[mf], bf[nf]);
        }
    }

    // Epilogue: c0,c1 at (row, 2*tig), c2,c3 at (row+8, 2*tig)
#pragma unroll
    for (int mf = 0; mf < 4; mf++) {
        int row = blockRow + warpM * 64 + mf * 16 + gid;
#pragma unroll
        for (int nf = 0; nf < 4; nf++) {
            int col = blockCol + warpN * 32 + nf * 8 + tig * 2;
            *(float2*)(Cm + (size_t)row * NSTATE + col) =
                make_float2(c[mf][nf][0], c[mf][nf][1]);
            *(float2*)(Cm + (size_t)(row + 8) * NSTATE + col) =
                make_float2(c[mf][nf][2], c[mf][nf][3]);
        }
    }
}

// ─── u (fp32) -> fp16, pure bandwidth pass ─────────────────────────────────
__global__ __launch_bounds__(256) void convert_u_f16(
    const float* __restrict__ in, __half* __restrict__ out)
{
    size_t t = (size_t)blockIdx.x * 256 + threadIdx.x;   // one float4 each
    float4 v = *(const float4*)(in + t * 4);
    __half2* o = (__half2*)(out + t * 4);
    o[0] = __floats2half2_rn(v.x, v.y);
    o[1] = __floats2half2_rn(v.z, v.w);
}

// ─── 256x256 transpose + convert to half (tiny) ────────────────────────────
__global__ __launch_bounds__(256) void transpose256_f16(
    const float* __restrict__ in, __half* __restrict__ out)
{
    int n = blockIdx.x;          // output row
    int k = threadIdx.x;         // output col
    out[n * 256 + k] = __float2half_rn(in[k * 256 + n]);
}

// ─── Scan phase 1: per-chunk local scan (zero init) ────────────────────────
__global__ __launch_bounds__(NK) void scan_partial(const float* __restrict__ A)
{
    const int k  = threadIdx.x;
    const int ch = blockIdx.x;
    const int b  = blockIdx.y;
    const float c = A[4 * k + 0];
    const float s = A[4 * k + 1];

    const float2* base = reinterpret_cast<const float2*>(g_uB)
                       + (size_t)(b * LEN + ch * LC) * NK + k;
    float zx = 0.f, zy = 0.f;
#pragma unroll 8
    for (int l = 0; l < LC; l++) {
        float2 w = base[(size_t)l * NK];
        float nx = fmaf(zx, c, fmaf(-zy, s, w.x));
        float ny = fmaf(zx, s, fmaf( zy, c, w.y));
        zx = nx; zy = ny;
    }
    g_h[((size_t)b * NCH + ch) * NK + k] = make_float2(zx, zy);
}

// ─── Scan phase 2: cross-chunk prefix (R^LC via double-prec doubling) ──────
__global__ __launch_bounds__(NK) void scan_prefix(
    const float* __restrict__ A, const float* __restrict__ x0)
{
    const int k = threadIdx.x;
    const int b = blockIdx.x;

    double cd = (double)A[4 * k + 0];
    double sd = (double)A[4 * k + 1];
#pragma unroll
    for (int i = 0; i < LOG2LC; i++) {
        double nc = cd * cd - sd * sd;
        double ns = 2.0 * cd * sd;
        cd = nc; sd = ns;
    }
    const float Cc = (float)cd, Ss = (float)sd;

    float zx = x0[((size_t)b * NK + k) * 2 + 0];
    float zy = x0[((size_t)b * NK + k) * 2 + 1];
    for (int ch = 0; ch < NCH; ch++) {
        size_t idx = ((size_t)b * NCH + ch) * NK + k;
        g_init[idx] = make_float2(zx, zy);
        float2 h = g_h[idx];
        float nx = fmaf(zx, Cc, fmaf(-zy, Ss, h.x));
        float ny = fmaf(zx, Ss, fmaf( zy, Cc, h.y));
        zx = nx; zy = ny;
    }
}

// ─── Scan phase 3: replay, write x (fp16) and new_state (fp32) ─────────────
__global__ __launch_bounds__(NK) void scan_replay(
    const float* __restrict__ A, float* __restrict__ out)
{
    const int k  = threadIdx.x;
    const int ch = blockIdx.x;
    const int b  = blockIdx.y;
    const float c = A[4 * k + 0];
    const float s = A[4 * k + 1];

    const size_t idx = ((size_t)b * NCH + ch) * NK + k;
    float2 z0 = g_init[idx];
    float zx = z0.x, zy = z0.y;

    const float2* src = reinterpret_cast<const float2*>(g_uB)
                      + (size_t)(b * LEN + ch * LC) * NK + k;
    __half2* dst = reinterpret_cast<__half2*>(g_xh)
                 + (size_t)(b * LEN + ch * LC) * NK + k;

#pragma unroll 8
    for (int l = 0; l < LC; l++) {
        float2 w = src[(size_t)l * NK];
        float nx = fmaf(zx, c, fmaf(-zy, s, w.x));
        float ny = fmaf(zx, s, fmaf( zy, c, w.y));
        zx = nx; zy = ny;
        dst[(size_t)l * NK] = __floats2half2_rn(zx, zy);
    }
    if (ch == NCH - 1) {
        out[OUT_Y + ((size_t)b * NK + k) * 2 + 0] = zx;
        out[OUT_Y + ((size_t)b * NK + k) * 2 + 1] = zy;
    }
}

// ─── Launch ────────────────────────────────────────────────────────────────
extern "C" void kernel_launch(void* const* d_in, const int* in_sizes, int n_in,
                              void* d_out, int out_size)
{
    const float* u  = (const float*)d_in[0];
    const float* x0 = (const float*)d_in[1];
    const float* A  = (const float*)d_in[2];
    const float* B  = (const float*)d_in[3];
    const float* C  = (const float*)d_in[4];
    float* out = (float*)d_out;
    (void)in_sizes; (void)n_in; (void)out_size;

    float  *uBp;
    __half *uhp, *xhp, *Bthp, *Cthp;
    cudaGetSymbolAddress((void**)&uBp,  g_uB);
    cudaGetSymbolAddress((void**)&uhp,  g_uh);
    cudaGetSymbolAddress((void**)&xhp,  g_xh);
    cudaGetSymbolAddress((void**)&Bthp, g_Bth);
    cudaGetSymbolAddress((void**)&Cthp, g_Cth);

    cudaFuncSetAttribute(gemm_f16, cudaFuncAttributeMaxDynamicSharedMemorySize, SMEM_BYTES);

    transpose256_f16<<<NSTATE, NSTATE>>>(B, Bthp);
    transpose256_f16<<<NSTATE, NSTATE>>>(C, Cthp);
    convert_u_f16<<<((size_t)M_TOTAL * NSTATE / 4 + 255) / 256, 256>>>(u, uhp);

    dim3 gemm_grid(NSTATE / BN, M_TOTAL / BM);     // (2, 256)
    gemm_f16<<<gemm_grid, 256, SMEM_BYTES>>>(uhp, Bthp, uBp);

    scan_partial<<<dim3(NCH, BATCH), NK>>>(A);
    scan_prefix<<<BATCH, NK>>>(A, x0);
    scan_replay<<<dim3(NCH, BATCH), NK>>>(A, out);

    gemm_f16<<<gemm_grid, 256, SMEM_BYTES>>>(xhp, Cthp, out);
}